// round 16
// baseline (speedup 1.0000x reference)
#include <cuda_runtime.h>

#define BATCH   262144
#define NIND    32
#define NDEP    16
#define EPSV    1e-7f
#define ITERS   2

typedef unsigned long long u64;

// ---- packed f32x2 helpers (Blackwell sm_103a) ----
__device__ __forceinline__ u64 pack2(float a, float b) {
    u64 r; asm("mov.b64 %0, {%1, %2};" : "=l"(r) : "f"(a), "f"(b)); return r;
}
__device__ __forceinline__ u64 dup2(float a) {
    u64 r; asm("mov.b64 %0, {%1, %1};" : "=l"(r) : "f"(a)); return r;
}
__device__ __forceinline__ void unpack2(u64 v, float &a, float &b) {
    asm("mov.b64 {%0, %1}, %2;" : "=f"(a), "=f"(b) : "l"(v));
}
__device__ __forceinline__ u64 ffma2(u64 a, u64 b, u64 c) {
    u64 d; asm("fma.rn.f32x2 %0, %1, %2, %3;" : "=l"(d) : "l"(a), "l"(b), "l"(c));
    return d;
}
__device__ __forceinline__ u64 mul2(u64 a, u64 b) {
    u64 d; asm("mul.rn.f32x2 %0, %1, %2;" : "=l"(d) : "l"(a), "l"(b));
    return d;
}
__device__ __forceinline__ float frcp(float x) {
    float r; asm("rcp.approx.f32 %0, %1;" : "=f"(r) : "f"(x)); return r;
}

// Pre-transformed weights: row-paired u64 for direct f32x2 operands.
struct CWeights {
    ulonglong2 W2[2 * NIND][4];   // [k][q2]: rows (4q2..4q2+3) paired; k<32->Bmat, else Theta
    ulonglong2 L2[NIND][4];       // Lam
    ulonglong2 Off2[NDEP][4];     // column j, rows paired; +Gamma off-diag, 0 diag
    u64 Gd2[8];                   // (1+eps - Gamma_ii) pairs
    u64 Ups2[8];
};

__device__ CWeights g_scratch;    // written by prep kernel
__constant__ CWeights cw;         // copied from g_scratch before main kernel

// ---- prep kernel: transform raw weights into g_scratch layout ----
__global__ void prep_kernel(const float* __restrict__ Ups, const float* __restrict__ Bm,
                            const float* __restrict__ Th,  const float* __restrict__ Ga,
                            const float* __restrict__ La)
{
    const int tid = threadIdx.x;
    for (int idx = tid; idx < 2 * NIND * 8; idx += 64) {
        int k = idx >> 3, j2 = idx & 7;
        int r0 = 2 * j2, r1 = r0 + 1;
        float w0, w1;
        if (k < NIND) { w0 = Bm[r0 * NIND + k];          w1 = Bm[r1 * NIND + k]; }
        else          { w0 = Th[r0 * NIND + (k - NIND)]; w1 = Th[r1 * NIND + (k - NIND)]; }
        ((u64*)&g_scratch.W2[k][0])[j2] = pack2(w0, w1);
    }
    for (int idx = tid; idx < NIND * 8; idx += 64) {
        int k = idx >> 3, j2 = idx & 7;
        ((u64*)&g_scratch.L2[k][0])[j2] =
            pack2(La[(2 * j2) * NIND + k], La[(2 * j2 + 1) * NIND + k]);
    }
    for (int idx = tid; idx < NDEP * 8; idx += 64) {
        int j = idx >> 3, i2 = idx & 7;
        int i0 = 2 * i2, i1 = i0 + 1;
        float v0 = (i0 == j) ? 0.0f : Ga[i0 * NDEP + j];
        float v1 = (i1 == j) ? 0.0f : Ga[i1 * NDEP + j];
        ((u64*)&g_scratch.Off2[j][0])[i2] = pack2(v0, v1);
    }
    if (tid < 8) {
        g_scratch.Ups2[tid] = pack2(Ups[2 * tid], Ups[2 * tid + 1]);
        g_scratch.Gd2[tid]  = pack2(1.0f + EPSV - Ga[(2 * tid) * NDEP + 2 * tid],
                                    1.0f + EPSV - Ga[(2 * tid + 1) * NDEP + 2 * tid + 1]);
    }
}

#define ROWSTRIDE 33   // floats per staged row (conflict-free scalar access)
#define TPB       64   // threads per block
#define EPT       2    // elements per thread (halves the LDC-port floor)

// Phases 2+3 for ONE element (cc-form Neumann). Live set ~64 GPRs.
__device__ __forceinline__ void solve_one(const u64* __restrict__ rhs,
                                          const u64* __restrict__ dd,
                                          float* __restrict__ o)
{
    u64 inv[8], y[8], cc[8];
#pragma unroll
    for (int q = 0; q < 8; ++q) {
        float g0, g1; unpack2(cw.Gd2[q], g0, g1);
        float d0, d1; unpack2(dd[q], d0, d1);
        inv[q] = pack2(frcp(g0 - d0), frcp(g1 - d1));
        cc[q]  = mul2(inv[q], rhs[q]);
        y[q]   = cc[q];
    }
#pragma unroll
    for (int it = 0; it < ITERS; ++it) {
        u64 acc[8];
#pragma unroll
        for (int q = 0; q < 8; ++q) acc[q] = 0ull;
#pragma unroll
        for (int j = 0; j < NDEP; ++j) {
            float a0, a1; unpack2(y[j >> 1], a0, a1);
            u64 yd = dup2((j & 1) ? a1 : a0);
#pragma unroll
            for (int q2 = 0; q2 < 4; ++q2) {
                ulonglong2 ow = cw.Off2[j][q2];         // warp-uniform LDC
                acc[2 * q2]     = ffma2(yd, ow.x, acc[2 * q2]);
                acc[2 * q2 + 1] = ffma2(yd, ow.y, acc[2 * q2 + 1]);
            }
        }
#pragma unroll
        for (int q = 0; q < 8; ++q) y[q] = ffma2(inv[q], acc[q], cc[q]);
    }
    ulonglong2* v = (ulonglong2*)o;
#pragma unroll
    for (int q = 0; q < 4; ++q) v[q] = make_ulonglong2(y[2 * q], y[2 * q + 1]);
}

// TWO elements per thread (R7 phase-1: each weight LDC feeds both elements,
// LDC-port floor ~15us) + SEQUENTIAL per-element solve (R9 structure) so the
// phase-3 live set is 96 GPRs instead of 128 -> lb(64,8) -> 16 warps/SM
// (R7 had 10.7). All weights stay on the constant port (cheapest broadcast:
// LDC.128=2cyc/SM; smem=4; LDG far worse — calibrated R6-R14).
__global__ __launch_bounds__(TPB, 8)
void clefo_kernel(const float* __restrict__ X, const float* __restrict__ Z,
                  float* __restrict__ out)
{
    __shared__ float sStage[TPB * EPT * ROWSTRIDE]; // block slab of X or Z (reused)

    const int tid = threadIdx.x;
    const size_t base = (size_t)blockIdx.x * (TPB * EPT);

    // ---- stage X slab (coalesced global -> padded smem) ----
    {
        const float4* src = (const float4*)(X + base * NIND);
#pragma unroll
        for (int i = 0; i < 8 * EPT; ++i) {
            int idx = tid + TPB * i;                 // float4 index in slab
            float4 v = src[idx];
            int row = idx >> 3, c0 = (idx & 7) << 2;
            float* dst = &sStage[row * ROWSTRIDE + c0];
            dst[0] = v.x; dst[1] = v.y; dst[2] = v.z; dst[3] = v.w;
        }
    }
    __syncthreads();

    const float* row0 = &sStage[(tid      ) * ROWSTRIDE];
    const float* row1 = &sStage[(tid + TPB) * ROWSTRIDE];

    // ---- Phase 1a: X-loop  (rhs += Bm*x ; d = La*x), rows packed in pairs
    u64 rhs0[8], rhs1[8], dd0[8], dd1[8];
#pragma unroll
    for (int q = 0; q < 8; ++q) {
        rhs0[q] = cw.Ups2[q]; rhs1[q] = cw.Ups2[q];
        dd0[q] = 0ull;        dd1[q] = 0ull;
    }

#pragma unroll
    for (int k = 0; k < NIND; ++k) {
        u64 xd0 = dup2(row0[k]);
        u64 xd1 = dup2(row1[k]);
#pragma unroll
        for (int q2 = 0; q2 < 4; ++q2) {
            ulonglong2 w = cw.W2[k][q2];             // one LDC feeds 4 FFMA2
            rhs0[2 * q2]     = ffma2(xd0, w.x, rhs0[2 * q2]);
            rhs0[2 * q2 + 1] = ffma2(xd0, w.y, rhs0[2 * q2 + 1]);
            rhs1[2 * q2]     = ffma2(xd1, w.x, rhs1[2 * q2]);
            rhs1[2 * q2 + 1] = ffma2(xd1, w.y, rhs1[2 * q2 + 1]);
            ulonglong2 l = cw.L2[k][q2];
            dd0[2 * q2]      = ffma2(xd0, l.x, dd0[2 * q2]);
            dd0[2 * q2 + 1]  = ffma2(xd0, l.y, dd0[2 * q2 + 1]);
            dd1[2 * q2]      = ffma2(xd1, l.x, dd1[2 * q2]);
            dd1[2 * q2 + 1]  = ffma2(xd1, l.y, dd1[2 * q2 + 1]);
        }
    }
    __syncthreads();

    // ---- stage Z slab (reuse buffer) ----
    {
        const float4* src = (const float4*)(Z + base * NIND);
#pragma unroll
        for (int i = 0; i < 8 * EPT; ++i) {
            int idx = tid + TPB * i;
            float4 v = src[idx];
            int r = idx >> 3, c0 = (idx & 7) << 2;
            float* dst = &sStage[r * ROWSTRIDE + c0];
            dst[0] = v.x; dst[1] = v.y; dst[2] = v.z; dst[3] = v.w;
        }
    }
    __syncthreads();

    // ---- Phase 1b: Z-loop  (rhs += Theta*z)
#pragma unroll
    for (int kz = 0; kz < NIND; ++kz) {
        int k = NIND + kz;
        u64 xd0 = dup2(row0[kz]);
        u64 xd1 = dup2(row1[kz]);
#pragma unroll
        for (int q2 = 0; q2 < 4; ++q2) {
            ulonglong2 w = cw.W2[k][q2];
            rhs0[2 * q2]     = ffma2(xd0, w.x, rhs0[2 * q2]);
            rhs0[2 * q2 + 1] = ffma2(xd0, w.y, rhs0[2 * q2 + 1]);
            rhs1[2 * q2]     = ffma2(xd1, w.x, rhs1[2 * q2]);
            rhs1[2 * q2 + 1] = ffma2(xd1, w.y, rhs1[2 * q2 + 1]);
        }
    }

    // ---- Phases 2+3: sequential per element (peak ~96 live GPRs, not 128)
    solve_one(rhs0, dd0, out + (base + tid) * NDEP);
    solve_one(rhs1, dd1, out + (base + TPB + tid) * NDEP);
}

extern "C" void kernel_launch(void* const* d_in, const int* in_sizes, int n_in,
                              void* d_out, int out_size)
{
    const float* X  = (const float*)d_in[0];
    const float* Z  = (const float*)d_in[1];
    const float* Up = (const float*)d_in[2];
    const float* Bm = (const float*)d_in[3];
    const float* Th = (const float*)d_in[4];
    const float* Ga = (const float*)d_in[5];
    const float* La = (const float*)d_in[6];
    float* out = (float*)d_out;

    // 1) transform weights into device scratch
    prep_kernel<<<1, 64>>>(Up, Bm, Th, Ga, La);

    // 2) copy transformed weights into the constant bank (D2D, capturable)
    void* sp = nullptr;
    cudaGetSymbolAddress(&sp, g_scratch);
    cudaMemcpyToSymbolAsync(cw, sp, sizeof(CWeights), 0,
                            cudaMemcpyDeviceToDevice, 0);

    // 3) main kernel: two elements per thread
    const int blocks = BATCH / (TPB * EPT);
    clefo_kernel<<<blocks, TPB>>>(X, Z, out);
}

// round 17
// speedup vs baseline: 1.8923x; 1.8923x over previous
#include <cuda_runtime.h>

#define BATCH   262144
#define NIND    32
#define NDEP    16
#define EPSV    1e-7f
#define ITERS   2

typedef unsigned long long u64;

// ---- packed f32x2 helpers (Blackwell sm_103a) ----
__device__ __forceinline__ u64 pack2(float a, float b) {
    u64 r; asm("mov.b64 %0, {%1, %2};" : "=l"(r) : "f"(a), "f"(b)); return r;
}
__device__ __forceinline__ u64 dup2(float a) {
    u64 r; asm("mov.b64 %0, {%1, %1};" : "=l"(r) : "f"(a)); return r;
}
__device__ __forceinline__ void unpack2(u64 v, float &a, float &b) {
    asm("mov.b64 {%0, %1}, %2;" : "=f"(a), "=f"(b) : "l"(v));
}
__device__ __forceinline__ u64 ffma2(u64 a, u64 b, u64 c) {
    u64 d; asm("fma.rn.f32x2 %0, %1, %2, %3;" : "=l"(d) : "l"(a), "l"(b), "l"(c));
    return d;
}
__device__ __forceinline__ u64 mul2(u64 a, u64 b) {
    u64 d; asm("mul.rn.f32x2 %0, %1, %2;" : "=l"(d) : "l"(a), "l"(b));
    return d;
}
__device__ __forceinline__ float frcp(float x) {
    float r; asm("rcp.approx.f32 %0, %1;" : "=f"(r) : "f"(x)); return r;
}

// Pre-transformed weights: row-paired u64 for direct f32x2 operands.
struct CWeights {
    ulonglong2 W2[2 * NIND][4];   // [k][q2]: rows (4q2..4q2+3) paired; k<32->Bmat, else Theta
    ulonglong2 L2[NIND][4];       // Lam
    ulonglong2 Off2[NDEP][4];     // column j, rows paired; +Gamma off-diag, 0 diag
    u64 Gd2[8];                   // (1+eps - Gamma_ii) pairs
    u64 Ups2[8];
};

__device__ CWeights g_scratch;    // written by prep kernel
__constant__ CWeights cw;         // copied from g_scratch before main kernels

// Mid buffer between phase-1 and solve kernels, TRANSPOSED for coalescing:
// slot s<4: (rhs[2s], rhs[2s+1]);  s>=4: (dd[2(s-4)], dd[2(s-4)+1])
__device__ ulonglong2 g_mid[8 * BATCH];   // 32 MB static scratch

// ---- prep kernel: transform raw weights into g_scratch layout ----
__global__ void prep_kernel(const float* __restrict__ Ups, const float* __restrict__ Bm,
                            const float* __restrict__ Th,  const float* __restrict__ Ga,
                            const float* __restrict__ La)
{
    const int tid = threadIdx.x;
    for (int idx = tid; idx < 2 * NIND * 8; idx += 64) {
        int k = idx >> 3, j2 = idx & 7;
        int r0 = 2 * j2, r1 = r0 + 1;
        float w0, w1;
        if (k < NIND) { w0 = Bm[r0 * NIND + k];          w1 = Bm[r1 * NIND + k]; }
        else          { w0 = Th[r0 * NIND + (k - NIND)]; w1 = Th[r1 * NIND + (k - NIND)]; }
        ((u64*)&g_scratch.W2[k][0])[j2] = pack2(w0, w1);
    }
    for (int idx = tid; idx < NIND * 8; idx += 64) {
        int k = idx >> 3, j2 = idx & 7;
        ((u64*)&g_scratch.L2[k][0])[j2] =
            pack2(La[(2 * j2) * NIND + k], La[(2 * j2 + 1) * NIND + k]);
    }
    for (int idx = tid; idx < NDEP * 8; idx += 64) {
        int j = idx >> 3, i2 = idx & 7;
        int i0 = 2 * i2, i1 = i0 + 1;
        float v0 = (i0 == j) ? 0.0f : Ga[i0 * NDEP + j];
        float v1 = (i1 == j) ? 0.0f : Ga[i1 * NDEP + j];
        ((u64*)&g_scratch.Off2[j][0])[i2] = pack2(v0, v1);
    }
    if (tid < 8) {
        g_scratch.Ups2[tid] = pack2(Ups[2 * tid], Ups[2 * tid + 1]);
        g_scratch.Gd2[tid]  = pack2(1.0f + EPSV - Ga[(2 * tid) * NDEP + 2 * tid],
                                    1.0f + EPSV - Ga[(2 * tid + 1) * NDEP + 2 * tid + 1]);
    }
}

#define ROWSTRIDE 33   // floats per staged row (conflict-free scalar access)
#define TPA       64   // phase-1 kernel: threads per block
#define EPT       2    // phase-1 kernel: elements per thread (LDC amortization)
#define TPB_S     128  // solve kernel: threads per block, one element each

// ============ KERNEL A: phase 1 (rhs, dd) — EPT=2, LDC floor halved ========
__global__ __launch_bounds__(TPA, 6)
void phase1_kernel(const float* __restrict__ X, const float* __restrict__ Z)
{
    __shared__ float sStage[TPA * EPT * ROWSTRIDE]; // block slab of X or Z (reused)

    const int tid = threadIdx.x;
    const size_t base = (size_t)blockIdx.x * (TPA * EPT);

    // ---- stage X slab (coalesced global -> padded smem) ----
    {
        const float4* src = (const float4*)(X + base * NIND);
#pragma unroll
        for (int i = 0; i < 8 * EPT; ++i) {
            int idx = tid + TPA * i;
            float4 v = src[idx];
            int row = idx >> 3, c0 = (idx & 7) << 2;
            float* dst = &sStage[row * ROWSTRIDE + c0];
            dst[0] = v.x; dst[1] = v.y; dst[2] = v.z; dst[3] = v.w;
        }
    }
    __syncthreads();

    const float* row0 = &sStage[(tid      ) * ROWSTRIDE];
    const float* row1 = &sStage[(tid + TPA) * ROWSTRIDE];

    u64 rhs0[8], rhs1[8], dd0[8], dd1[8];
#pragma unroll
    for (int q = 0; q < 8; ++q) {
        rhs0[q] = cw.Ups2[q]; rhs1[q] = cw.Ups2[q];
        dd0[q] = 0ull;        dd1[q] = 0ull;
    }

#pragma unroll
    for (int k = 0; k < NIND; ++k) {
        u64 xd0 = dup2(row0[k]);
        u64 xd1 = dup2(row1[k]);
#pragma unroll
        for (int q2 = 0; q2 < 4; ++q2) {
            ulonglong2 w = cw.W2[k][q2];             // one LDC feeds 4 FFMA2
            rhs0[2 * q2]     = ffma2(xd0, w.x, rhs0[2 * q2]);
            rhs0[2 * q2 + 1] = ffma2(xd0, w.y, rhs0[2 * q2 + 1]);
            rhs1[2 * q2]     = ffma2(xd1, w.x, rhs1[2 * q2]);
            rhs1[2 * q2 + 1] = ffma2(xd1, w.y, rhs1[2 * q2 + 1]);
            ulonglong2 l = cw.L2[k][q2];
            dd0[2 * q2]      = ffma2(xd0, l.x, dd0[2 * q2]);
            dd0[2 * q2 + 1]  = ffma2(xd0, l.y, dd0[2 * q2 + 1]);
            dd1[2 * q2]      = ffma2(xd1, l.x, dd1[2 * q2]);
            dd1[2 * q2 + 1]  = ffma2(xd1, l.y, dd1[2 * q2 + 1]);
        }
    }
    __syncthreads();

    // ---- stage Z slab (reuse buffer) ----
    {
        const float4* src = (const float4*)(Z + base * NIND);
#pragma unroll
        for (int i = 0; i < 8 * EPT; ++i) {
            int idx = tid + TPA * i;
            float4 v = src[idx];
            int r = idx >> 3, c0 = (idx & 7) << 2;
            float* dst = &sStage[r * ROWSTRIDE + c0];
            dst[0] = v.x; dst[1] = v.y; dst[2] = v.z; dst[3] = v.w;
        }
    }
    __syncthreads();

#pragma unroll
    for (int kz = 0; kz < NIND; ++kz) {
        int k = NIND + kz;
        u64 xd0 = dup2(row0[kz]);
        u64 xd1 = dup2(row1[kz]);
#pragma unroll
        for (int q2 = 0; q2 < 4; ++q2) {
            ulonglong2 w = cw.W2[k][q2];
            rhs0[2 * q2]     = ffma2(xd0, w.x, rhs0[2 * q2]);
            rhs0[2 * q2 + 1] = ffma2(xd0, w.y, rhs0[2 * q2 + 1]);
            rhs1[2 * q2]     = ffma2(xd1, w.x, rhs1[2 * q2]);
            rhs1[2 * q2 + 1] = ffma2(xd1, w.y, rhs1[2 * q2 + 1]);
        }
    }

    // ---- store to transposed mid buffer: fully coalesced STG.128 ----
    const size_t e0 = base + tid;
    const size_t e1 = base + TPA + tid;
#pragma unroll
    for (int s = 0; s < 4; ++s) {
        g_mid[s * BATCH + e0]       = make_ulonglong2(rhs0[2 * s], rhs0[2 * s + 1]);
        g_mid[s * BATCH + e1]       = make_ulonglong2(rhs1[2 * s], rhs1[2 * s + 1]);
        g_mid[(s + 4) * BATCH + e0] = make_ulonglong2(dd0[2 * s], dd0[2 * s + 1]);
        g_mid[(s + 4) * BATCH + e1] = make_ulonglong2(dd1[2 * s], dd1[2 * s + 1]);
    }
}

// ============ KERNEL B: solve (phases 2+3) — EPT=1, high occupancy =========
__global__ __launch_bounds__(TPB_S, 6)
void solve_kernel(float* __restrict__ out)
{
    const size_t e = (size_t)blockIdx.x * TPB_S + threadIdx.x;

    // ---- load rhs/dd from transposed mid buffer (coalesced LDG.128) ----
    u64 rhs[8], dd[8];
#pragma unroll
    for (int s = 0; s < 4; ++s) {
        ulonglong2 tr = g_mid[s * BATCH + e];
        rhs[2 * s] = tr.x; rhs[2 * s + 1] = tr.y;
        ulonglong2 td = g_mid[(s + 4) * BATCH + e];
        dd[2 * s] = td.x; dd[2 * s + 1] = td.y;
    }

    // ---- Phase 2: inv = 1/(Gd - d) ; cc = inv*rhs
    u64 inv[8], cc[8], y[8];
#pragma unroll
    for (int q = 0; q < 8; ++q) {
        float g0, g1; unpack2(cw.Gd2[q], g0, g1);
        float d0, d1; unpack2(dd[q], d0, d1);
        inv[q] = pack2(frcp(g0 - d0), frcp(g1 - d1));
        cc[q]  = mul2(inv[q], rhs[q]);
        y[q]   = cc[q];
    }

    // ---- Phase 3: Neumann  y <- cc + inv*(GammaOff*y)
#pragma unroll
    for (int it = 0; it < ITERS; ++it) {
        u64 acc[8];
#pragma unroll
        for (int q = 0; q < 8; ++q) acc[q] = 0ull;
#pragma unroll
        for (int j = 0; j < NDEP; ++j) {
            float a0, a1; unpack2(y[j >> 1], a0, a1);
            u64 yd = dup2((j & 1) ? a1 : a0);
#pragma unroll
            for (int q2 = 0; q2 < 4; ++q2) {
                ulonglong2 ow = cw.Off2[j][q2];       // warp-uniform LDC
                acc[2 * q2]     = ffma2(yd, ow.x, acc[2 * q2]);
                acc[2 * q2 + 1] = ffma2(yd, ow.y, acc[2 * q2 + 1]);
            }
        }
#pragma unroll
        for (int q = 0; q < 8; ++q) y[q] = ffma2(inv[q], acc[q], cc[q]);
    }

    // ---- Store: row-packed pairs are already in output order -> STG.128
    ulonglong2* ov = (ulonglong2*)(out + e * NDEP);
#pragma unroll
    for (int q = 0; q < 4; ++q) ov[q] = make_ulonglong2(y[2 * q], y[2 * q + 1]);
}

extern "C" void kernel_launch(void* const* d_in, const int* in_sizes, int n_in,
                              void* d_out, int out_size)
{
    const float* X  = (const float*)d_in[0];
    const float* Z  = (const float*)d_in[1];
    const float* Up = (const float*)d_in[2];
    const float* Bm = (const float*)d_in[3];
    const float* Th = (const float*)d_in[4];
    const float* Ga = (const float*)d_in[5];
    const float* La = (const float*)d_in[6];
    float* out = (float*)d_out;

    // 1) transform weights into device scratch
    prep_kernel<<<1, 64>>>(Up, Bm, Th, Ga, La);

    // 2) copy transformed weights into the constant bank (D2D, capturable)
    void* sp = nullptr;
    cudaGetSymbolAddress(&sp, g_scratch);
    cudaMemcpyToSymbolAsync(cw, sp, sizeof(CWeights), 0,
                            cudaMemcpyDeviceToDevice, 0);

    // 3) phase-1 kernel: EPT=2, low LDC floor, registers free to be ~150
    phase1_kernel<<<BATCH / (TPA * EPT), TPA>>>(X, Z);

    // 4) solve kernel: EPT=1, ~80 regs, high occupancy
    solve_kernel<<<BATCH / TPB_S, TPB_S>>>(out);
}